// round 10
// baseline (speedup 1.0000x reference)
#include <cuda_runtime.h>

#define B_ 4
#define N_ 128
#define L_ 20
#define D_ 512
#define KR (B_*L_)            // 80
#define SCALE 0.044194173824159216f   // 1/sqrt(512)

// ---- scratch (no allocation allowed) ----
__device__ float g_k[KR*D_];          // k  = f_w @ Wk^T + bk
__device__ float g_kk[KR*D_];         // kk = k @ Wq
__device__ float g_c[KR];             // c[l] = bq . k[l]
__device__ float g_fbq[B_*N_*D_];     // gated boundary features
__device__ float g_Ab[B_*N_*N_];      // boundary self-attention

// ============================================================
// Small-GEMM, no K-split: C[80,512] tile TM=8 x TN=32, 128 thr.
// ============================================================
template<bool TRANSB, bool BIAS, bool CEPI>
__global__ void __launch_bounds__(128)
gemm8(const float* __restrict__ A, const float* __restrict__ Bm,
      const float* __restrict__ bias, const float* __restrict__ bqv,
      float* __restrict__ C, float* __restrict__ cvec)
{
    const int Kd = D_, Nd = D_;
    int row0 = blockIdx.x * 8;     // gridx = 10
    int col0 = blockIdx.y * 32;    // gridy = 16

    __shared__ float As[8][33];
    __shared__ float Bs[32][36];

    int t = threadIdx.x;
    int c  = t & 31;
    int rh = t >> 5;               // 0..3 -> rows rh*2, rh*2+1

    float acc0 = 0.f, acc1 = 0.f;

    for (int k0 = 0; k0 < Kd; k0 += 32) {
        {
            int kc = t & 31, r2 = (t >> 5) * 2;
            As[r2][kc]     = A[(row0 + r2) * Kd + k0 + kc];
            As[r2 + 1][kc] = A[(row0 + r2 + 1) * Kd + k0 + kc];
        }
        if (TRANSB) {
            int cc = t >> 2, h = t & 3;
            const float4* bp = (const float4*)(Bm + (long)(col0 + cc) * Kd + k0 + h * 8);
            #pragma unroll
            for (int q = 0; q < 2; q++) {
                float4 v = bp[q];
                int kc = h * 8 + q * 4;
                Bs[kc][cc] = v.x; Bs[kc+1][cc] = v.y; Bs[kc+2][cc] = v.z; Bs[kc+3][cc] = v.w;
            }
        } else {
            #pragma unroll
            for (int p = 0; p < 2; p++) {
                int kc = (t >> 3) + p * 16;
                int c4 = (t & 7) * 4;
                float4 v = *(const float4*)(Bm + (long)(k0 + kc) * Nd + col0 + c4);
                Bs[kc][c4] = v.x; Bs[kc][c4+1] = v.y; Bs[kc][c4+2] = v.z; Bs[kc][c4+3] = v.w;
            }
        }
        __syncthreads();
        #pragma unroll
        for (int kc = 0; kc < 32; kc++) {
            float bv = Bs[kc][c];
            acc0 = fmaf(As[rh*2][kc],     bv, acc0);
            acc1 = fmaf(As[rh*2 + 1][kc], bv, acc1);
        }
        __syncthreads();
    }
    float bb = BIAS ? bias[col0 + c] : 0.f;
    C[(row0 + rh*2)     * Nd + col0 + c] = acc0 + bb;
    C[(row0 + rh*2 + 1) * Nd + col0 + c] = acc1 + bb;

    if (CEPI && blockIdx.y == 0) {
        __shared__ float cred[8][17];
        int r = t >> 4, seg = t & 15;
        float s = 0.f;
        const float4* kr  = (const float4*)(A + (long)(row0 + r) * Kd + seg * 32);
        const float4* bq4 = (const float4*)(bqv + seg * 32);
        #pragma unroll
        for (int q = 0; q < 8; q++) {
            float4 kv = kr[q], bv = bq4[q];
            s += kv.x*bv.x + kv.y*bv.y + kv.z*bv.z + kv.w*bv.w;
        }
        cred[r][seg] = s;
        __syncthreads();
        if (t < 8) {
            float tot = 0.f;
            #pragma unroll
            for (int q = 0; q < 16; q++) tot += cred[t][q];
            cvec[row0 + t] = tot;
        }
    }
}

// cross-attention (L=20) + sentence gating -> f_bq ; also out = f_b (init)
__global__ void __launch_bounds__(256) attn_kernel(const float* __restrict__ f_b,
                                                   const float* __restrict__ f_w,
                                                   const float* __restrict__ f_s,
                                                   float* __restrict__ out)
{
    int bn = blockIdx.x; int b = bn >> 7;
    __shared__ float fb[D_];
    __shared__ float sl[L_];
    int tid = threadIdx.x;
    fb[tid]       = f_b[bn*D_ + tid];
    fb[tid + 256] = f_b[bn*D_ + tid + 256];
    __syncthreads();
    int w = tid >> 5, lane = tid & 31;
    for (int l = w; l < L_; l += 8) {
        const float* kr = g_kk + (b*L_ + l) * D_;
        float p = 0.f;
        #pragma unroll
        for (int e = lane; e < D_; e += 32) p = fmaf(fb[e], kr[e], p);
        #pragma unroll
        for (int off = 16; off > 0; off >>= 1) p += __shfl_xor_sync(0xffffffffu, p, off);
        if (lane == 0) sl[l] = (p + g_c[b*L_ + l]) * SCALE;
    }
    __syncthreads();
    if (tid == 0) {
        float mx = sl[0];
        #pragma unroll
        for (int l = 1; l < L_; l++) mx = fmaxf(mx, sl[l]);
        float s = 0.f;
        #pragma unroll
        for (int l = 0; l < L_; l++) { float e = __expf(sl[l] - mx); sl[l] = e; s += e; }
        float inv = __fdividef(1.f, s);
        #pragma unroll
        for (int l = 0; l < L_; l++) sl[l] *= inv;
    }
    __syncthreads();
    for (int d = tid; d < D_; d += 256) {
        float acc = 0.f;
        #pragma unroll
        for (int l = 0; l < L_; l++) acc += sl[l] * f_w[(b*L_ + l)*D_ + d];
        g_fbq[bn*D_ + d] = fb[d] * (acc + f_s[b*D_ + d]);
        out[bn*D_ + d] = fb[d];          // init residual for final RED.ADD
    }
}

// ============================================================
// Fused score GEMM + row softmax, register-blocked.
// Tile 8 rows x 128 cols, 128 threads, 2x4 micro-tile.
// grid (16 row-tiles, 4 batches) = 64 blocks.
// ============================================================
__global__ void __launch_bounds__(128) score_softmax_f()
{
    int b = blockIdx.y;
    int row0 = blockIdx.x * 8;
    const float* Abase = g_fbq + (long)b * N_ * D_;

    __shared__ float As[32][9];       // [kc][row]
    __shared__ float Bs[32][132];     // [kc][col]
    __shared__ float Ssc[8][128];

    int t  = threadIdx.x;
    int tc = t & 31;                  // col group (4 cols)
    int tr = t >> 5;                  // 0..3 -> rows tr*2, tr*2+1

    float acc[2][4];
    #pragma unroll
    for (int i = 0; i < 2; i++)
        #pragma unroll
        for (int j = 0; j < 4; j++) acc[i][j] = 0.f;

    for (int k0 = 0; k0 < D_; k0 += 32) {
        // As: 8 rows x 32 kc; thread loads rows r and r+4 at kc = t&31
        {
            int kc = t & 31, r = t >> 5;
            As[kc][r]     = Abase[(row0 + r)     * D_ + k0 + kc];
            As[kc][r + 4] = Abase[(row0 + r + 4) * D_ + k0 + kc];
        }
        // Bs: 32 kc x 128 cols; thread t owns col t, reads 128B contiguous
        {
            const float4* bp = (const float4*)(Abase + (long)t * D_ + k0);
            #pragma unroll
            for (int q = 0; q < 8; q++) {
                float4 v = bp[q];
                int kc = q * 4;
                Bs[kc][t] = v.x; Bs[kc+1][t] = v.y; Bs[kc+2][t] = v.z; Bs[kc+3][t] = v.w;
            }
        }
        __syncthreads();
        #pragma unroll
        for (int kc = 0; kc < 32; kc++) {
            float a0 = As[kc][tr*2];
            float a1 = As[kc][tr*2 + 1];
            float4 bv = *(const float4*)&Bs[kc][tc * 4];
            acc[0][0] = fmaf(a0, bv.x, acc[0][0]); acc[0][1] = fmaf(a0, bv.y, acc[0][1]);
            acc[0][2] = fmaf(a0, bv.z, acc[0][2]); acc[0][3] = fmaf(a0, bv.w, acc[0][3]);
            acc[1][0] = fmaf(a1, bv.x, acc[1][0]); acc[1][1] = fmaf(a1, bv.y, acc[1][1]);
            acc[1][2] = fmaf(a1, bv.z, acc[1][2]); acc[1][3] = fmaf(a1, bv.w, acc[1][3]);
        }
        __syncthreads();
    }
    #pragma unroll
    for (int i = 0; i < 2; i++) {
        float4 v = make_float4(acc[i][0]*SCALE, acc[i][1]*SCALE,
                               acc[i][2]*SCALE, acc[i][3]*SCALE);
        *(float4*)&Ssc[tr*2 + i][tc * 4] = v;
    }
    __syncthreads();

    // softmax: warp w handles rows w*2, w*2+1
    int w = t >> 5, lane = t & 31;
    #pragma unroll
    for (int i = 0; i < 2; i++) {
        int r = w * 2 + i;
        float4 v = *(const float4*)&Ssc[r][lane * 4];
        float mx = fmaxf(fmaxf(v.x, v.y), fmaxf(v.z, v.w));
        #pragma unroll
        for (int off = 16; off > 0; off >>= 1) mx = fmaxf(mx, __shfl_xor_sync(0xffffffffu, mx, off));
        float e0 = __expf(v.x - mx), e1 = __expf(v.y - mx);
        float e2 = __expf(v.z - mx), e3 = __expf(v.w - mx);
        float s = e0 + e1 + e2 + e3;
        #pragma unroll
        for (int off = 16; off > 0; off >>= 1) s += __shfl_xor_sync(0xffffffffu, s, off);
        float inv = __fdividef(1.f, s);
        *(float4*)&g_Ab[((long)b*N_ + row0 + r) * N_ + lane * 4] =
            make_float4(e0*inv, e1*inv, e2*inv, e3*inv);
    }
}

// sigmoid(x) = 0.5*tanh(0.5x)+0.5 — 1 MUFU instead of 2
__device__ __forceinline__ float sigmoid_fast(float x)
{
    float t;
    asm("tanh.approx.f32 %0, %1;" : "=f"(t) : "f"(0.5f * x));
    return fmaf(0.5f, t, 0.5f);
}

// f_m streaming kernel, m-split x4; RED.ADD directly into out (out pre-inited to f_b).
__global__ void __launch_bounds__(512) final_split(const float* __restrict__ f_b,
                                                   const float* __restrict__ f_s,
                                                   const float* __restrict__ f_m,
                                                   float* __restrict__ out)
{
    int bidx  = blockIdx.x;          // 0..511
    int split = bidx & 3;
    int jg    = (bidx >> 2) & 31;
    int b     = bidx >> 7;
    int j0    = jg * 4;
    int m0    = split * 32;
    int d     = threadIdx.x;

    __shared__ float2 a2[4][32];     // {A_b[b][j][m], A_b[b][m][j]} for this m-chunk
    if (d < 128) {
        int jj = d >> 5, m = d & 31;
        a2[jj][m] = make_float2(g_Ab[(b*N_ + j0 + jj)*N_ + m0 + m],
                                g_Ab[(b*N_ + m0 + m)*N_ + j0 + jj]);
    }
    __syncthreads();

    float fsd = f_s[b*D_ + d];
    float acc[4] = {0.f, 0.f, 0.f, 0.f};
    const float* fmp = f_m + (((long)(b*N_ + m0))*N_ + j0)*D_ + d;
    const float* fbp = f_b + (b*N_ + m0)*D_ + d;

    #pragma unroll 4
    for (int m = 0; m < 32; m++) {
        float fbv = fbp[m*D_];
        #pragma unroll
        for (int jj = 0; jj < 4; jj++) {
            float x = fmp[(long)m*(N_*D_) + jj*D_];
            float2 a = a2[jj][m];
            float sg = sigmoid_fast(x * fsd);
            acc[jj] = fmaf(a.x, fbv, acc[jj]);
            acc[jj] = fmaf(a.y * sg, x, acc[jj]);
        }
    }
    #pragma unroll
    for (int jj = 0; jj < 4; jj++)
        atomicAdd(out + ((b*N_ + j0 + jj)*D_ + d), acc[jj]);
}

extern "C" void kernel_launch(void* const* d_in, const int* in_sizes, int n_in,
                              void* d_out, int out_size)
{
    const float* f_b = (const float*)d_in[0];
    const float* f_w = (const float*)d_in[1];
    const float* f_s = (const float*)d_in[2];
    const float* f_m = (const float*)d_in[3];
    const float* Wq  = (const float*)d_in[4];
    const float* bq  = (const float*)d_in[5];
    const float* Wk  = (const float*)d_in[6];
    const float* bk  = (const float*)d_in[7];
    float* out = (float*)d_out;

    void *p_k, *p_kk, *p_c;
    cudaGetSymbolAddress(&p_k,  g_k);
    cudaGetSymbolAddress(&p_kk, g_kk);
    cudaGetSymbolAddress(&p_c,  g_c);

    // 1) k = f_w @ Wk^T + bk            (TRANSB, bias)
    gemm8<true, true, false><<<dim3(10, 16), 128>>>(f_w, Wk, bk, nullptr,
                                                    (float*)p_k, nullptr);
    // 2) kk = k @ Wq ; c = bq . k       (NN, c-epilogue)
    gemm8<false, false, true><<<dim3(10, 16), 128>>>((const float*)p_k, Wq, nullptr, bq,
                                                     (float*)p_kk, (float*)p_c);
    // 3) cross-attn softmax + gating -> f_bq ; out = f_b
    attn_kernel<<<B_*N_, 256>>>(f_b, f_w, f_s, out);
    // 4) fused self-attn score GEMM + softmax -> A_b (register-blocked)
    score_softmax_f<<<dim3(16, 4), 128>>>();
    // 5) DRAM-bound f_m stream, m-split x4, RED.ADD into out
    final_split<<<512, 512>>>(f_b, f_s, f_m, out);
}

// round 11
// speedup vs baseline: 1.1483x; 1.1483x over previous
#include <cuda_runtime.h>

#define B_ 4
#define N_ 128
#define L_ 20
#define D_ 512
#define KR (B_*L_)            // 80
#define SCALE 0.044194173824159216f   // 1/sqrt(512)

// ---- scratch (no allocation allowed) ----
__device__ float g_k[KR*D_];          // k  = f_w @ Wk^T + bk
__device__ float g_kk[KR*D_];         // kk = k @ Wq
__device__ float g_c[KR];             // c[l] = bq . k[l]
__device__ float g_fbq[B_*N_*D_];     // gated boundary features
__device__ float g_Ab[B_*N_*N_];      // boundary self-attention
__device__ float g_part[B_*4*N_*N_];  // K-split partials of score GEMM

// ============================================================
// Small-GEMM, no K-split: C[80,512] tile TM=8 x TN=32, 128 thr.
// ============================================================
template<bool TRANSB, bool BIAS, bool CEPI>
__global__ void __launch_bounds__(128)
gemm8(const float* __restrict__ A, const float* __restrict__ Bm,
      const float* __restrict__ bias, const float* __restrict__ bqv,
      float* __restrict__ C, float* __restrict__ cvec)
{
    const int Kd = D_, Nd = D_;
    int row0 = blockIdx.x * 8;     // gridx = 10
    int col0 = blockIdx.y * 32;    // gridy = 16

    __shared__ float As[8][33];
    __shared__ float Bs[32][36];

    int t = threadIdx.x;
    int c  = t & 31;
    int rh = t >> 5;               // 0..3 -> rows rh*2, rh*2+1

    float acc0 = 0.f, acc1 = 0.f;

    for (int k0 = 0; k0 < Kd; k0 += 32) {
        {
            int kc = t & 31, r2 = (t >> 5) * 2;
            As[r2][kc]     = A[(row0 + r2) * Kd + k0 + kc];
            As[r2 + 1][kc] = A[(row0 + r2 + 1) * Kd + k0 + kc];
        }
        if (TRANSB) {
            int cc = t >> 2, h = t & 3;
            const float4* bp = (const float4*)(Bm + (long)(col0 + cc) * Kd + k0 + h * 8);
            #pragma unroll
            for (int q = 0; q < 2; q++) {
                float4 v = bp[q];
                int kc = h * 8 + q * 4;
                Bs[kc][cc] = v.x; Bs[kc+1][cc] = v.y; Bs[kc+2][cc] = v.z; Bs[kc+3][cc] = v.w;
            }
        } else {
            #pragma unroll
            for (int p = 0; p < 2; p++) {
                int kc = (t >> 3) + p * 16;
                int c4 = (t & 7) * 4;
                float4 v = *(const float4*)(Bm + (long)(k0 + kc) * Nd + col0 + c4);
                Bs[kc][c4] = v.x; Bs[kc][c4+1] = v.y; Bs[kc][c4+2] = v.z; Bs[kc][c4+3] = v.w;
            }
        }
        __syncthreads();
        #pragma unroll
        for (int kc = 0; kc < 32; kc++) {
            float bv = Bs[kc][c];
            acc0 = fmaf(As[rh*2][kc],     bv, acc0);
            acc1 = fmaf(As[rh*2 + 1][kc], bv, acc1);
        }
        __syncthreads();
    }
    float bb = BIAS ? bias[col0 + c] : 0.f;
    C[(row0 + rh*2)     * Nd + col0 + c] = acc0 + bb;
    C[(row0 + rh*2 + 1) * Nd + col0 + c] = acc1 + bb;

    if (CEPI && blockIdx.y == 0) {
        __shared__ float cred[8][17];
        int r = t >> 4, seg = t & 15;
        float s = 0.f;
        const float4* kr  = (const float4*)(A + (long)(row0 + r) * Kd + seg * 32);
        const float4* bq4 = (const float4*)(bqv + seg * 32);
        #pragma unroll
        for (int q = 0; q < 8; q++) {
            float4 kv = kr[q], bv = bq4[q];
            s += kv.x*bv.x + kv.y*bv.y + kv.z*bv.z + kv.w*bv.w;
        }
        cred[r][seg] = s;
        __syncthreads();
        if (t < 8) {
            float tot = 0.f;
            #pragma unroll
            for (int q = 0; q < 16; q++) tot += cred[t][q];
            cvec[row0 + t] = tot;
        }
    }
}

// ============================================================
// R2-proven K-split partial GEMM (TRANSB only), 16x128 tile,
// 128 threads, 4x4 micro-tile. Used for the score GEMM.
// ============================================================
__global__ void __launch_bounds__(128)
gemm_part_nt(const float* __restrict__ A, const float* __restrict__ B,
             float* __restrict__ Cpart, int M, int Ncol, int K, int ldB,
             int nsplit, int strideA, int strideB)
{
    const int TM = 16, TN = 128, KC = 16;
    int batch = blockIdx.z / nsplit;
    int split = blockIdx.z - batch * nsplit;
    int klen  = K / nsplit;
    int kbase = split * klen;
    A += (long)batch * strideA;
    B += (long)batch * strideB;
    float* C = Cpart + (long)(batch * nsplit + split) * M * Ncol;

    __shared__ float As[KC][TM];
    __shared__ float Bs[KC][TN];

    int row0 = blockIdx.x * TM;
    int col0 = 0;                       // Ncol == TN here
    int tid = threadIdx.x;
    int tr = tid >> 5;
    int tc = tid & 31;

    float acc[4][4];
    #pragma unroll
    for (int i = 0; i < 4; i++)
        #pragma unroll
        for (int j = 0; j < 4; j++) acc[i][j] = 0.f;

    for (int kb = 0; kb < klen; kb += KC) {
        int k0 = kbase + kb;
        {
            int idx = tid * 2;
            int r = idx >> 4, kc = idx & 15;
            float2 av = *(const float2*)(A + (long)(row0 + r) * K + k0 + kc);
            As[kc][r]     = av.x;
            As[kc + 1][r] = av.y;
        }
        {
            const float* bp = B + (long)(col0 + tid) * ldB + k0;
            #pragma unroll
            for (int q = 0; q < 4; q++) {
                float4 v = *(const float4*)(bp + q * 4);
                Bs[q*4+0][tid] = v.x; Bs[q*4+1][tid] = v.y;
                Bs[q*4+2][tid] = v.z; Bs[q*4+3][tid] = v.w;
            }
        }
        __syncthreads();
        #pragma unroll
        for (int kc = 0; kc < KC; kc++) {
            float4 a4 = ((const float4*)As[kc])[tr];
            float4 b4 = ((const float4*)Bs[kc])[tc];
            acc[0][0] += a4.x*b4.x; acc[0][1] += a4.x*b4.y; acc[0][2] += a4.x*b4.z; acc[0][3] += a4.x*b4.w;
            acc[1][0] += a4.y*b4.x; acc[1][1] += a4.y*b4.y; acc[1][2] += a4.y*b4.z; acc[1][3] += a4.y*b4.w;
            acc[2][0] += a4.z*b4.x; acc[2][1] += a4.z*b4.y; acc[2][2] += a4.z*b4.z; acc[2][3] += a4.z*b4.w;
            acc[3][0] += a4.w*b4.x; acc[3][1] += a4.w*b4.y; acc[3][2] += a4.w*b4.z; acc[3][3] += a4.w*b4.w;
        }
        __syncthreads();
    }
    #pragma unroll
    for (int i = 0; i < 4; i++) {
        int row = row0 + tr * 4 + i;
        float4 v = make_float4(acc[i][0], acc[i][1], acc[i][2], acc[i][3]);
        *(float4*)(C + (long)row * Ncol + col0 + tc * 4) = v;
    }
}

// sum score partials, scale, row softmax -> A_b   (R2-proven)
__global__ void __launch_bounds__(128) score_softmax()
{
    int bn = blockIdx.x; int b = bn >> 7; int n = bn & 127;
    int m = threadIdx.x;
    float s = 0.f;
    #pragma unroll
    for (int sp = 0; sp < 4; sp++) s += g_part[(((b*4 + sp)*N_) + n)*N_ + m];
    s *= SCALE;
    __shared__ float red[4];
    float mx = s;
    #pragma unroll
    for (int off = 16; off > 0; off >>= 1) mx = fmaxf(mx, __shfl_xor_sync(0xffffffffu, mx, off));
    if ((m & 31) == 0) red[m >> 5] = mx;
    __syncthreads();
    mx = fmaxf(fmaxf(red[0], red[1]), fmaxf(red[2], red[3]));
    float e = __expf(s - mx);
    __syncthreads();
    float sm = e;
    #pragma unroll
    for (int off = 16; off > 0; off >>= 1) sm += __shfl_xor_sync(0xffffffffu, sm, off);
    if ((m & 31) == 0) red[m >> 5] = sm;
    __syncthreads();
    sm = red[0] + red[1] + red[2] + red[3];
    g_Ab[bn*N_ + m] = e * __fdividef(1.f, sm);
}

// cross-attention (L=20) + sentence gating -> f_bq ; also out = f_b (init)
__global__ void __launch_bounds__(256) attn_kernel(const float* __restrict__ f_b,
                                                   const float* __restrict__ f_w,
                                                   const float* __restrict__ f_s,
                                                   float* __restrict__ out)
{
    int bn = blockIdx.x; int b = bn >> 7;
    __shared__ float fb[D_];
    __shared__ float sl[L_];
    int tid = threadIdx.x;
    fb[tid]       = f_b[bn*D_ + tid];
    fb[tid + 256] = f_b[bn*D_ + tid + 256];
    __syncthreads();
    int w = tid >> 5, lane = tid & 31;
    for (int l = w; l < L_; l += 8) {
        const float* kr = g_kk + (b*L_ + l) * D_;
        float p = 0.f;
        #pragma unroll
        for (int e = lane; e < D_; e += 32) p = fmaf(fb[e], kr[e], p);
        #pragma unroll
        for (int off = 16; off > 0; off >>= 1) p += __shfl_xor_sync(0xffffffffu, p, off);
        if (lane == 0) sl[l] = (p + g_c[b*L_ + l]) * SCALE;
    }
    __syncthreads();
    if (tid == 0) {
        float mx = sl[0];
        #pragma unroll
        for (int l = 1; l < L_; l++) mx = fmaxf(mx, sl[l]);
        float s = 0.f;
        #pragma unroll
        for (int l = 0; l < L_; l++) { float e = __expf(sl[l] - mx); sl[l] = e; s += e; }
        float inv = __fdividef(1.f, s);
        #pragma unroll
        for (int l = 0; l < L_; l++) sl[l] *= inv;
    }
    __syncthreads();
    for (int d = tid; d < D_; d += 256) {
        float acc = 0.f;
        #pragma unroll
        for (int l = 0; l < L_; l++) acc += sl[l] * f_w[(b*L_ + l)*D_ + d];
        g_fbq[bn*D_ + d] = fb[d] * (acc + f_s[b*D_ + d]);
        out[bn*D_ + d] = fb[d];          // init residual for final RED.ADD
    }
}

// sigmoid(x) = 0.5*tanh(0.5x)+0.5 — 1 MUFU instead of 2
__device__ __forceinline__ float sigmoid_fast(float x)
{
    float t;
    asm("tanh.approx.f32 %0, %1;" : "=f"(t) : "f"(0.5f * x));
    return fmaf(0.5f, t, 0.5f);
}

// f_m streaming kernel, m-split x4; RED.ADD directly into out (out pre-inited to f_b).
__global__ void __launch_bounds__(512) final_split(const float* __restrict__ f_b,
                                                   const float* __restrict__ f_s,
                                                   const float* __restrict__ f_m,
                                                   float* __restrict__ out)
{
    int bidx  = blockIdx.x;          // 0..511
    int split = bidx & 3;
    int jg    = (bidx >> 2) & 31;
    int b     = bidx >> 7;
    int j0    = jg * 4;
    int m0    = split * 32;
    int d     = threadIdx.x;

    __shared__ float2 a2[4][32];     // {A_b[b][j][m], A_b[b][m][j]} for this m-chunk
    if (d < 128) {
        int jj = d >> 5, m = d & 31;
        a2[jj][m] = make_float2(g_Ab[(b*N_ + j0 + jj)*N_ + m0 + m],
                                g_Ab[(b*N_ + m0 + m)*N_ + j0 + jj]);
    }
    __syncthreads();

    float fsd = f_s[b*D_ + d];
    float acc[4] = {0.f, 0.f, 0.f, 0.f};
    const float* fmp = f_m + (((long)(b*N_ + m0))*N_ + j0)*D_ + d;
    const float* fbp = f_b + (b*N_ + m0)*D_ + d;

    #pragma unroll 4
    for (int m = 0; m < 32; m++) {
        float fbv = fbp[m*D_];
        #pragma unroll
        for (int jj = 0; jj < 4; jj++) {
            float x = fmp[(long)m*(N_*D_) + jj*D_];
            float2 a = a2[jj][m];
            float sg = sigmoid_fast(x * fsd);
            acc[jj] = fmaf(a.x, fbv, acc[jj]);
            acc[jj] = fmaf(a.y * sg, x, acc[jj]);
        }
    }
    #pragma unroll
    for (int jj = 0; jj < 4; jj++)
        atomicAdd(out + ((b*N_ + j0 + jj)*D_ + d), acc[jj]);
}

extern "C" void kernel_launch(void* const* d_in, const int* in_sizes, int n_in,
                              void* d_out, int out_size)
{
    const float* f_b = (const float*)d_in[0];
    const float* f_w = (const float*)d_in[1];
    const float* f_s = (const float*)d_in[2];
    const float* f_m = (const float*)d_in[3];
    const float* Wq  = (const float*)d_in[4];
    const float* bq  = (const float*)d_in[5];
    const float* Wk  = (const float*)d_in[6];
    const float* bk  = (const float*)d_in[7];
    float* out = (float*)d_out;

    void *p_k, *p_kk, *p_c, *p_fbq, *p_part;
    cudaGetSymbolAddress(&p_k,    g_k);
    cudaGetSymbolAddress(&p_kk,   g_kk);
    cudaGetSymbolAddress(&p_c,    g_c);
    cudaGetSymbolAddress(&p_fbq,  g_fbq);
    cudaGetSymbolAddress(&p_part, g_part);

    // 1) k = f_w @ Wk^T + bk            (TRANSB, bias)
    gemm8<true, true, false><<<dim3(10, 16), 128>>>(f_w, Wk, bk, nullptr,
                                                    (float*)p_k, nullptr);
    // 2) kk = k @ Wq ; c = bq . k       (NN, c-epilogue)
    gemm8<false, false, true><<<dim3(10, 16), 128>>>((const float*)p_k, Wq, nullptr, bq,
                                                     (float*)p_kk, (float*)p_c);
    // 3) cross-attn softmax + gating -> f_bq ; out = f_b
    attn_kernel<<<B_*N_, 256>>>(f_b, f_w, f_s, out);
    // 4) self-attn score partials (R2-proven: K-split 4, batched)
    gemm_part_nt<<<dim3(8, 1, 16), 128>>>((const float*)p_fbq, (const float*)p_fbq,
                                          (float*)p_part, N_, N_, D_, D_, 4,
                                          N_*D_, N_*D_);
    // 5) partial-sum + row softmax -> A_b
    score_softmax<<<B_*N_, 128>>>();
    // 6) DRAM-bound f_m stream, m-split x4, RED.ADD into out
    final_split<<<512, 512>>>(f_b, f_s, f_m, out);
}